// round 13
// baseline (speedup 1.0000x reference)
#include <cuda_runtime.h>

#define K1v 16
#define BATCH 16
#define CH 32
#define NP 4096
#define EDG (NP*K1v)          // 65536
#define TP 16                 // points per CTA
#define RR 256                // rows per CTA
#define INVC 0.9999950000374997f  // 1/sqrt(1+1e-5)

typedef unsigned long long u64;

// Scratch (no cudaMalloc allowed)
__device__ int   g_idx[BATCH*NP*K1v];            // 4 MB
__device__ __align__(16) float g_featT[BATCH*NP*CH];   // 8 MB (B,P,C)
__device__ int   g_brk[BATCH*256];
__device__ __align__(16) float g_wPre[4096];     // [c][128o]: ss0*W0h | ss0*W0l | ssc*SW
__device__ __align__(16) float g_w1T[1024];      // W1 [k][32o]
__device__ __align__(16) float g_w2T[2048];      // W2 [k][64o]
__device__ __align__(16) float gY0[BATCH*NP*32]; // ss0*(W0h f)   8 MB
__device__ __align__(16) float gA [BATCH*NP*32]; // pb0 - Y0s     8 MB
__device__ __align__(16) float gSC[BATCH*NP*64]; // shortcut     16 MB

__device__ __forceinline__ u64 fma2(u64 a, u64 b, u64 c) {
    u64 d;
    asm("fma.rn.f32x2 %0, %1, %2, %3;" : "=l"(d) : "l"(a), "l"(b), "l"(c));
    return d;
}
__device__ __forceinline__ u64 add2(u64 a, u64 b) {
    u64 d;
    asm("add.rn.f32x2 %0, %1, %2;" : "=l"(d) : "l"(a), "l"(b));
    return d;
}
__device__ __forceinline__ u64 pack2(float x, float y) {
    u64 d;
    asm("mov.b64 %0, {%1, %2};" : "=l"(d) : "f"(x), "f"(y));
    return d;
}
__device__ __forceinline__ void unpack2(u64 v, float& x, float& y) {
    asm("mov.b64 {%0, %1}, %2;" : "=f"(x), "=f"(y) : "l"(v));
}

// ---------------------------------------------------------------------------
// Weight prep: g_wPre [c][128] (scales folded), g_w1T/g_w2T [k][o]
// ---------------------------------------------------------------------------
__global__ void wprep_kernel(const float* __restrict__ W0, const float* __restrict__ W1,
                             const float* __restrict__ W2, const float* __restrict__ SW,
                             const float* __restrict__ g0, const float* __restrict__ sg) {
    int t = blockIdx.x * 256 + threadIdx.x;   // 0..7167
    if (t < 4096) {
        int c = t >> 7, j = t & 127;
        float v;
        if (j < 32)       v = g0[j] * INVC * W0[j * 64 + 32 + c];        // Y0s weights
        else if (j < 64)  { int o = j - 32; v = g0[o] * INVC * W0[o * 64 + c]; }  // pb0 weights
        else              { int o = j - 64; v = sg[o] * INVC * SW[o * 32 + c]; }  // shortcut
        g_wPre[t] = v;
    } else if (t < 5120) {
        int i = t - 4096, k = i >> 5, o = i & 31;
        g_w1T[k * 32 + o] = W1[o * 32 + k];
    } else if (t < 7168) {
        int i = t - 5120, k = i >> 6, o = i & 63;
        g_w2T[k * 64 + o] = W2[o * 32 + k];
    }
}

// ---------------------------------------------------------------------------
// Per-point precompute: Y0s, A = pb0 - Y0s, SC  (one thread per point)
// ---------------------------------------------------------------------------
__global__ void __launch_bounds__(128) pre_kernel(const float* __restrict__ bb0,
                                                  const float* __restrict__ sbc) {
    int pid = blockIdx.x * 128 + threadIdx.x;     // 0 .. B*P-1
    const float* fp = g_featT + (size_t)pid * 32;
    float f[32];
    #pragma unroll
    for (int i = 0; i < 8; i++) {
        float4 v = *(const float4*)(fp + i * 4);
        f[4*i] = v.x; f[4*i+1] = v.y; f[4*i+2] = v.z; f[4*i+3] = v.w;
    }
    u64 acc[32];
    #pragma unroll
    for (int j = 0; j < 32; j++) acc[j] = 0ull;
    #pragma unroll 4
    for (int c = 0; c < 32; c++) {
        u64 xc = pack2(f[c], f[c]);
        const ulonglong2* w = (const ulonglong2*)(g_wPre + c * 128);
        #pragma unroll
        for (int t = 0; t < 16; t++) {
            ulonglong2 wv = w[t];
            acc[2*t]   = fma2(wv.x, xc, acc[2*t]);
            acc[2*t+1] = fma2(wv.y, xc, acc[2*t+1]);
        }
    }
    // Y0s = acc[0..15]
    {
        ulonglong2* oy = (ulonglong2*)(gY0 + (size_t)pid * 32);
        #pragma unroll
        for (int j = 0; j < 8; j++) { ulonglong2 v; v.x = acc[2*j]; v.y = acc[2*j+1]; oy[j] = v; }
    }
    // A = (PBraw + sb0) - Y0s
    {
        float av[32];
        #pragma unroll
        for (int j = 0; j < 16; j++) {
            float pl, ph, yl, yh;
            unpack2(acc[16 + j], pl, ph);
            unpack2(acc[j], yl, yh);
            av[2*j]   = pl + bb0[2*j]   - yl;
            av[2*j+1] = ph + bb0[2*j+1] - yh;
        }
        float4* oa = (float4*)(gA + (size_t)pid * 32);
        #pragma unroll
        for (int j = 0; j < 8; j++)
            oa[j] = make_float4(av[4*j], av[4*j+1], av[4*j+2], av[4*j+3]);
    }
    // pass B: shortcut SC (64 o)
    #pragma unroll
    for (int j = 0; j < 32; j++) acc[j] = 0ull;
    #pragma unroll 4
    for (int c = 0; c < 32; c++) {
        u64 xc = pack2(f[c], f[c]);
        const ulonglong2* w = (const ulonglong2*)(g_wPre + c * 128 + 64);
        #pragma unroll
        for (int t = 0; t < 16; t++) {
            ulonglong2 wv = w[t];
            acc[2*t]   = fma2(wv.x, xc, acc[2*t]);
            acc[2*t+1] = fma2(wv.y, xc, acc[2*t+1]);
        }
    }
    {
        float4* os = (float4*)(gSC + (size_t)pid * 64);
        #pragma unroll
        for (int j = 0; j < 16; j++) {
            float x0, x1, x2, x3;
            unpack2(acc[2*j],   x0, x1);
            unpack2(acc[2*j+1], x2, x3);
            os[j] = make_float4(x0 + sbc[4*j], x1 + sbc[4*j+1],
                                x2 + sbc[4*j+2], x3 + sbc[4*j+3]);
        }
    }
}

// ---------------------------------------------------------------------------
// Edge preprocessing: prep (defaults + per-chunk break) -> scatter
// ---------------------------------------------------------------------------
__global__ void prep_kernel(const int* __restrict__ ef) {
    const int blk   = blockIdx.x;
    const int b     = blk >> 8;
    const int chunk = blk & 255;
    const int t     = threadIdx.x;
    const int e     = chunk * 256 + t;

    g_idx[(b << 16) | e] = NP - K1v + (e & 15);

    const int* __restrict__ pf = ef + (size_t)b * 2 * EDG;
    int brk = EDG;
    if (e > 0 && pf[e] == 0 && pf[e - 1] != 0) brk = e;

    __shared__ int s[256];
    s[t] = brk;
    __syncthreads();
    #pragma unroll
    for (int off = 128; off > 0; off >>= 1) {
        if (t < off) s[t] = min(s[t], s[t + off]);
        __syncthreads();
    }
    if (t == 0) g_brk[b * 256 + chunk] = s[0];
}

__global__ void scatter_kernel(const int* __restrict__ ef) {
    const int b  = blockIdx.y;
    const int e0 = blockIdx.x * 256;
    const int t  = threadIdx.x;
    const int e  = e0 + t;
    const int* __restrict__ pf = ef + (size_t)b * 2 * EDG;
    const int* __restrict__ tg = pf + EDG;

    __shared__ int s[272];
    __shared__ int sm2[256];
    sm2[t] = g_brk[b * 256 + t];
    for (int i = t; i < 272; i += 256) {
        int src = e0 - 16 + i;
        s[i] = (src >= 0) ? pf[src] : -1;
    }
    __syncthreads();
    #pragma unroll
    for (int off = 128; off > 0; off >>= 1) {
        if (t < off) sm2[t] = min(sm2[t], sm2[t + off]);
        __syncthreads();
    }
    const int broken = sm2[0];

    int v = s[t + 16];
    int j = 0, m = e, si = t + 16;
    while (m > 0 && j < 16 && s[si - 1] == v) { m--; si--; j++; }
    if (j < 16 && e < broken && (unsigned)v < (unsigned)NP)
        g_idx[(((size_t)b * NP + v) << 4) + j] = tg[e];
}

// ---------------------------------------------------------------------------
// Transpose features (B,C,P) -> (B,P,C)
// ---------------------------------------------------------------------------
__global__ void transpose_kernel(const float* __restrict__ f) {
    __shared__ float tile[32][33];
    int b  = blockIdx.y;
    int p0 = blockIdx.x * 32;
    int tx = threadIdx.x, ty = threadIdx.y;  // (32, 8)
    #pragma unroll
    for (int i = 0; i < 32; i += 8)
        tile[ty + i][tx] = f[((size_t)b * CH + ty + i) * NP + p0 + tx];
    __syncthreads();
    #pragma unroll
    for (int i = 0; i < 32; i += 8)
        g_featT[((size_t)b * NP + p0 + ty + i) * CH + tx] = tile[tx][ty + i];
}

// ---------------------------------------------------------------------------
// GEMM stage (R12-proven): o-sliced warps; weights = [k][o] uniform LDG.128.
// MODE 1: dst[o][r] = relu(acc*s + b[o]);
// MODE 2: red[o][pt] = sum over rows of relu(acc*s + b[o])
// ---------------------------------------------------------------------------
template<int MODE>
__device__ __forceinline__ void gemm_stage(
    const float* __restrict__ src,   // [32][256] smem
    float*       __restrict__ dst,   // smem
    const float* __restrict__ WkT,   // global, [k][Ototal]
    int OSTR, int o0,
    const float* __restrict__ scal, const float* __restrict__ bias,
    int lane)
{
    u64 acc[8][4];
    #pragma unroll
    for (int o = 0; o < 8; o++)
        #pragma unroll
        for (int j = 0; j < 4; j++) acc[o][j] = 0ull;

    const float* xb = src + lane * 4;
    const float* wb = WkT + o0;

    #pragma unroll 4
    for (int k = 0; k < 32; k++) {
        u64 xp[4];
        {
            ulonglong2 x0 = *(const ulonglong2*)(xb + k * RR);
            ulonglong2 x1 = *(const ulonglong2*)(xb + k * RR + 128);
            xp[0] = x0.x; xp[1] = x0.y; xp[2] = x1.x; xp[3] = x1.y;
        }
        const float4* w4 = (const float4*)(wb + k * OSTR);
        float4 wa = __ldg(w4);
        float4 wc = __ldg(w4 + 1);
        u64 wd[8] = { pack2(wa.x,wa.x), pack2(wa.y,wa.y),
                      pack2(wa.z,wa.z), pack2(wa.w,wa.w),
                      pack2(wc.x,wc.x), pack2(wc.y,wc.y),
                      pack2(wc.z,wc.z), pack2(wc.w,wc.w) };
        #pragma unroll
        for (int o = 0; o < 8; o++) {
            acc[o][0] = fma2(wd[o], xp[0], acc[o][0]);
            acc[o][1] = fma2(wd[o], xp[1], acc[o][1]);
            acc[o][2] = fma2(wd[o], xp[2], acc[o][2]);
            acc[o][3] = fma2(wd[o], xp[3], acc[o][3]);
        }
    }

    const int ptq = lane >> 2;

    #pragma unroll
    for (int o = 0; o < 8; o++) {
        int og = o0 + o;
        float s = scal[og];
        float bv = bias[og];
        if (MODE == 2) {
            #pragma unroll
            for (int g = 0; g < 2; g++) {
                float h0, h1, h2, h3;
                unpack2(acc[o][2*g],   h0, h1);
                unpack2(acc[o][2*g+1], h2, h3);
                float pa = fmaxf(fmaf(h0, s, bv), 0.f) + fmaxf(fmaf(h1, s, bv), 0.f)
                         + fmaxf(fmaf(h2, s, bv), 0.f) + fmaxf(fmaf(h3, s, bv), 0.f);
                pa += __shfl_xor_sync(0xffffffffu, pa, 1);
                pa += __shfl_xor_sync(0xffffffffu, pa, 2);
                if ((lane & 3) == 0)
                    dst[og * TP + g * 8 + ptq] = pa;
            }
        } else {
            #pragma unroll
            for (int g = 0; g < 2; g++) {
                float h0, h1, h2, h3;
                unpack2(acc[o][2*g],   h0, h1);
                unpack2(acc[o][2*g+1], h2, h3);
                h0 = fmaxf(fmaf(h0, s, bv), 0.f);
                h1 = fmaxf(fmaf(h1, s, bv), 0.f);
                h2 = fmaxf(fmaf(h2, s, bv), 0.f);
                h3 = fmaxf(fmaf(h3, s, bv), 0.f);
                *(float4*)(dst + og * RR + g * 128 + lane * 4)
                    = make_float4(h0, h1, h2, h3);
            }
        }
    }
}

// ---------------------------------------------------------------------------
// Main kernel, 128 threads, TP=16 points (256 rows), 3 CTAs/SM.
// Smem (float offsets), 17600 floats = 68.75 KB:
//   0 ss1  32 sb1  64 ss2  128 sb2  192 red[64][16]  1216 XA  9408 XB
// ---------------------------------------------------------------------------
#define SMEM_FLOATS 17600

__global__ void __launch_bounds__(128, 3) main_kernel(
    const float* __restrict__ g1, const float* __restrict__ bb1,
    const float* __restrict__ g2, const float* __restrict__ bb2,
    float* __restrict__ out)
{
    extern __shared__ float sm[];
    float* ss1 = sm;
    float* sb1 = sm + 32;
    float* ss2 = sm + 64;
    float* sb2 = sm + 128;
    float* red = sm + 192;
    float* XA  = sm + 1216;
    float* XB  = sm + 9408;

    const int tid  = threadIdx.x;
    const int base = blockIdx.x * TP;
    const int b    = base >> 12;
    const int p0   = base & (NP - 1);

    if (tid < 32)      { ss1[tid] = g1[tid] * INVC; sb1[tid] = bb1[tid]; }
    else if (tid < 96) { int o = tid - 32; ss2[o] = g2[o] * INVC; sb2[o] = bb2[o]; }

    // ---- staging: h0 = relu(Y0s[q] + A[p]) directly into XB [o][r] ----
    {
        int r0s = tid * 2;
        int pt  = r0s >> 4;
        int k0  = r0s & 15;
        size_t rowp = (size_t)b * NP + (p0 + pt);
        int2 qq = *(const int2*)(g_idx + (rowp << 4) + k0);
        const ulonglong2* Ap  = (const ulonglong2*)(gA  + rowp * 32);
        const ulonglong2* Yq0 = (const ulonglong2*)(gY0 + ((size_t)b * NP + qq.x) * 32);
        const ulonglong2* Yq1 = (const ulonglong2*)(gY0 + ((size_t)b * NP + qq.y) * 32);
        #pragma unroll
        for (int jj = 0; jj < 8; jj++) {
            ulonglong2 av = Ap[jj];
            ulonglong2 y0 = Yq0[jj];
            ulonglong2 y1 = Yq1[jj];
            int o = jj * 4;
            {
                u64 c0 = add2(y0.x, av.x), c1 = add2(y1.x, av.x);
                float a0, b0_, a1, b1_;
                unpack2(c0, a0, b0_); unpack2(c1, a1, b1_);
                *(u64*)(XB + (o+0) * RR + r0s) = pack2(fmaxf(a0, 0.f), fmaxf(a1, 0.f));
                *(u64*)(XB + (o+1) * RR + r0s) = pack2(fmaxf(b0_, 0.f), fmaxf(b1_, 0.f));
            }
            {
                u64 c0 = add2(y0.y, av.y), c1 = add2(y1.y, av.y);
                float a0, b0_, a1, b1_;
                unpack2(c0, a0, b0_); unpack2(c1, a1, b1_);
                *(u64*)(XB + (o+2) * RR + r0s) = pack2(fmaxf(a0, 0.f), fmaxf(a1, 0.f));
                *(u64*)(XB + (o+3) * RR + r0s) = pack2(fmaxf(b0_, 0.f), fmaxf(b1_, 0.f));
            }
        }
    }
    __syncthreads();

    const int w_   = tid >> 5;
    const int lane = tid & 31;

    gemm_stage<1>(XB, XA, g_w1T, 32, w_ * 8, ss1, sb1, lane);
    __syncthreads();
    gemm_stage<2>(XA, red, g_w2T, 64, w_ * 8,      ss2, sb2, lane);
    gemm_stage<2>(XA, red, g_w2T, 64, 32 + w_ * 8, ss2, sb2, lane);
    __syncthreads();

    // ---- epilogue: out = relu(SC[p] + mean) ----
    {
        int pt  = tid & 15;
        int o0s = (tid >> 4) * 8;
        const float4* scp = (const float4*)(gSC + ((size_t)b * NP + p0 + pt) * 64 + o0s);
        float4 s0 = scp[0], s1 = scp[1];
        float scv[8] = { s0.x, s0.y, s0.z, s0.w, s1.x, s1.y, s1.z, s1.w };
        #pragma unroll
        for (int j = 0; j < 8; j++) {
            int o = o0s + j;
            float v = scv[j] + red[o * TP + pt] * (1.0f / 16.0f);
            out[((size_t)b * 64 + o) * NP + p0 + pt] = fmaxf(v, 0.f);
        }
    }
}

// ---------------------------------------------------------------------------
extern "C" void kernel_launch(void* const* d_in, const int* in_sizes, int n_in,
                              void* d_out, int out_size)
{
    (void)in_sizes; (void)n_in; (void)out_size;
    const float* features = (const float*)d_in[1];
    const int*   ef       = (const int*)d_in[2];

    static bool attr_set = false;
    if (!attr_set) {
        cudaFuncSetAttribute(main_kernel,
                             cudaFuncAttributeMaxDynamicSharedMemorySize,
                             SMEM_FLOATS * (int)sizeof(float));
        attr_set = true;
    }

    wprep_kernel<<<28, 256>>>((const float*)d_in[3], (const float*)d_in[6],
                              (const float*)d_in[9], (const float*)d_in[12],
                              (const float*)d_in[4], (const float*)d_in[13]);
    prep_kernel<<<BATCH * 256, 256>>>(ef);
    {
        dim3 tg(EDG / 256, BATCH);
        scatter_kernel<<<tg, 256>>>(ef);
    }
    {
        dim3 tb(32, 8), tg(NP / 32, BATCH);
        transpose_kernel<<<tg, tb>>>(features);
    }
    pre_kernel<<<(BATCH * NP) / 128, 128>>>((const float*)d_in[5],
                                            (const float*)d_in[14]);
    main_kernel<<<(BATCH * NP) / TP, 128, SMEM_FLOATS * sizeof(float)>>>(
        (const float*)d_in[7],  (const float*)d_in[8],
        (const float*)d_in[10], (const float*)d_in[11],
        (float*)d_out);
}

// round 14
// speedup vs baseline: 1.1157x; 1.1157x over previous
#include <cuda_runtime.h>

#define K1v 16
#define BATCH 16
#define CH 32
#define NP 4096
#define EDG (NP*K1v)          // 65536
#define TP 16                 // points per CTA
#define RR 256                // rows per CTA
#define INVC 0.9999950000374997f  // 1/sqrt(1+1e-5)

typedef unsigned long long u64;

// Scratch (no cudaMalloc allowed)
__device__ int   g_idx[BATCH*NP*K1v];                  // 4 MB
__device__ __align__(16) float g_featT[BATCH*NP*CH];   // 8 MB (B,P,C)
__device__ int   g_brk[BATCH*256];
__device__ __align__(16) float g_wPre[4096];     // [c][128o]: ss0*W0h | ss0*W0l | ssc*SW
__device__ __align__(16) float g_w1T[1024];      // (g1*INVC)*W1   [k][32o]
__device__ __align__(16) float g_w2T[2048];      // (g2*INVC/16)*W2 [k][64o]
__device__ __align__(16) float gY0[BATCH*NP*32]; // ss0*(W0h f)   8 MB
__device__ __align__(16) float gA [BATCH*NP*32]; // pb0 - Y0s     8 MB
__device__ __align__(16) float gSC[BATCH*NP*64]; // shortcut     16 MB

__device__ __forceinline__ u64 fma2(u64 a, u64 b, u64 c) {
    u64 d;
    asm("fma.rn.f32x2 %0, %1, %2, %3;" : "=l"(d) : "l"(a), "l"(b), "l"(c));
    return d;
}
__device__ __forceinline__ u64 add2(u64 a, u64 b) {
    u64 d;
    asm("add.rn.f32x2 %0, %1, %2;" : "=l"(d) : "l"(a), "l"(b));
    return d;
}
__device__ __forceinline__ u64 pack2(float x, float y) {
    u64 d;
    asm("mov.b64 %0, {%1, %2};" : "=l"(d) : "f"(x), "f"(y));
    return d;
}
__device__ __forceinline__ void unpack2(u64 v, float& x, float& y) {
    asm("mov.b64 {%0, %1}, %2;" : "=f"(x), "=f"(y) : "l"(v));
}

// ---------------------------------------------------------------------------
// Weight prep: g_wPre [c][128] (scales folded); w1T/w2T [k][o] scale-folded.
// ---------------------------------------------------------------------------
__global__ void wprep_kernel(const float* __restrict__ W0, const float* __restrict__ W1,
                             const float* __restrict__ W2, const float* __restrict__ SW,
                             const float* __restrict__ g0, const float* __restrict__ sg,
                             const float* __restrict__ g1, const float* __restrict__ g2) {
    int t = blockIdx.x * 256 + threadIdx.x;   // 0..7167
    if (t < 4096) {
        int c = t >> 7, j = t & 127;
        float v;
        if (j < 32)       v = g0[j] * INVC * W0[j * 64 + 32 + c];
        else if (j < 64)  { int o = j - 32; v = g0[o] * INVC * W0[o * 64 + c]; }
        else              { int o = j - 64; v = sg[o] * INVC * SW[o * 32 + c]; }
        g_wPre[t] = v;
    } else if (t < 5120) {
        int i = t - 4096, k = i >> 5, o = i & 31;
        g_w1T[k * 32 + o] = g1[o] * INVC * W1[o * 32 + k];
    } else if (t < 7168) {
        int i = t - 5120, k = i >> 6, o = i & 63;
        g_w2T[k * 64 + o] = g2[o] * (INVC / 16.0f) * W2[o * 32 + k];
    }
}

// ---------------------------------------------------------------------------
// Edge preprocessing: prep (defaults + per-chunk break) -> scatter
// ---------------------------------------------------------------------------
__global__ void prep_kernel(const int* __restrict__ ef) {
    const int blk   = blockIdx.x;
    const int b     = blk >> 8;
    const int chunk = blk & 255;
    const int t     = threadIdx.x;
    const int e     = chunk * 256 + t;

    g_idx[(b << 16) | e] = NP - K1v + (e & 15);

    const int* __restrict__ pf = ef + (size_t)b * 2 * EDG;
    int brk = EDG;
    if (e > 0 && pf[e] == 0 && pf[e - 1] != 0) brk = e;

    __shared__ int s[256];
    s[t] = brk;
    __syncthreads();
    #pragma unroll
    for (int off = 128; off > 0; off >>= 1) {
        if (t < off) s[t] = min(s[t], s[t + off]);
        __syncthreads();
    }
    if (t == 0) g_brk[b * 256 + chunk] = s[0];
}

__global__ void scatter_kernel(const int* __restrict__ ef) {
    const int b  = blockIdx.y;
    const int e0 = blockIdx.x * 256;
    const int t  = threadIdx.x;
    const int e  = e0 + t;
    const int* __restrict__ pf = ef + (size_t)b * 2 * EDG;
    const int* __restrict__ tg = pf + EDG;

    __shared__ int s[272];
    __shared__ int sm2[256];
    sm2[t] = g_brk[b * 256 + t];
    for (int i = t; i < 272; i += 256) {
        int src = e0 - 16 + i;
        s[i] = (src >= 0) ? pf[src] : -1;
    }
    __syncthreads();
    #pragma unroll
    for (int off = 128; off > 0; off >>= 1) {
        if (t < off) sm2[t] = min(sm2[t], sm2[t + off]);
        __syncthreads();
    }
    const int broken = sm2[0];

    int v = s[t + 16];
    int j = 0, m = e, si = t + 16;
    while (m > 0 && j < 16 && s[si - 1] == v) { m--; si--; j++; }
    if (j < 16 && e < broken && (unsigned)v < (unsigned)NP)
        g_idx[(((size_t)b * NP + v) << 4) + j] = tg[e];
}

// ---------------------------------------------------------------------------
// FUSED transpose + per-point precompute.
// Block (32,8) handles 32 points: transpose into tile[c][pt], write featT,
// then compute 128 outputs/pt (Y0s | pb0raw | SCraw) from tile, and emit
// gY0 / gA / gSC.  Weight rows are warp-uniform LDG.128; tile reads LDS.
// ---------------------------------------------------------------------------
__global__ void __launch_bounds__(256) transpre_kernel(
    const float* __restrict__ f,
    const float* __restrict__ bb0, const float* __restrict__ sbc)
{
    __shared__ float tile[32][33];
    __shared__ float obuf[128][33];

    const int b  = blockIdx.y;
    const int p0 = blockIdx.x * 32;
    const int tx = threadIdx.x, ty = threadIdx.y;  // (32, 8)
    const int tid = ty * 32 + tx;

    #pragma unroll
    for (int i = 0; i < 32; i += 8)
        tile[ty + i][tx] = f[((size_t)b * CH + ty + i) * NP + p0 + tx];
    __syncthreads();
    #pragma unroll
    for (int i = 0; i < 32; i += 8)
        g_featT[((size_t)b * NP + p0 + ty + i) * CH + tx] = tile[tx][ty + i];

    // compute 16 outputs (j0..j0+15) for point tx
    {
        const int j0 = ty * 16;
        float acc[16];
        #pragma unroll
        for (int j = 0; j < 16; j++) acc[j] = 0.f;
        #pragma unroll 4
        for (int c = 0; c < 32; c++) {
            float fc = tile[c][tx];
            const float4* w4 = (const float4*)(g_wPre + c * 128 + j0);
            #pragma unroll
            for (int q = 0; q < 4; q++) {
                float4 w = __ldg(w4 + q);
                acc[q*4+0] = fmaf(w.x, fc, acc[q*4+0]);
                acc[q*4+1] = fmaf(w.y, fc, acc[q*4+1]);
                acc[q*4+2] = fmaf(w.z, fc, acc[q*4+2]);
                acc[q*4+3] = fmaf(w.w, fc, acc[q*4+3]);
            }
        }
        #pragma unroll
        for (int j = 0; j < 16; j++) obuf[j0 + j][tx] = acc[j];
    }
    __syncthreads();

    const size_t rowbase = (size_t)b * NP + p0;
    for (int i = tid; i < 1024; i += 256) {
        int pt = i >> 5, c = i & 31;
        float y = obuf[c][pt];
        gY0[(rowbase + pt) * 32 + c] = y;
        gA [(rowbase + pt) * 32 + c] = obuf[32 + c][pt] + bb0[c] - y;
    }
    for (int i = tid; i < 2048; i += 256) {
        int pt = i >> 6, o = i & 63;
        gSC[(rowbase + pt) * 64 + o] = obuf[64 + o][pt] + sbc[o];
    }
}

// ---------------------------------------------------------------------------
// GEMM stage (scales pre-folded): o-sliced warps; weights [k][o] uniform
// LDG.128.  MODE 1: dst[o][r] = relu(acc + b[o]);
//           MODE 2: red[o][pt] = sum over rows of relu(acc + b[o])
// ---------------------------------------------------------------------------
template<int MODE>
__device__ __forceinline__ void gemm_stage(
    const float* __restrict__ src,   // [32][256] smem
    float*       __restrict__ dst,   // smem
    const float* __restrict__ WkT,   // global, [k][Ototal]
    int OSTR, int o0,
    const float* __restrict__ bias,
    int lane)
{
    u64 acc[8][4];
    #pragma unroll
    for (int o = 0; o < 8; o++)
        #pragma unroll
        for (int j = 0; j < 4; j++) acc[o][j] = 0ull;

    const float* xb = src + lane * 4;
    const float* wb = WkT + o0;

    #pragma unroll 4
    for (int k = 0; k < 32; k++) {
        u64 xp[4];
        {
            ulonglong2 x0 = *(const ulonglong2*)(xb + k * RR);
            ulonglong2 x1 = *(const ulonglong2*)(xb + k * RR + 128);
            xp[0] = x0.x; xp[1] = x0.y; xp[2] = x1.x; xp[3] = x1.y;
        }
        const float4* w4 = (const float4*)(wb + k * OSTR);
        float4 wa = __ldg(w4);
        float4 wc = __ldg(w4 + 1);
        u64 wd[8] = { pack2(wa.x,wa.x), pack2(wa.y,wa.y),
                      pack2(wa.z,wa.z), pack2(wa.w,wa.w),
                      pack2(wc.x,wc.x), pack2(wc.y,wc.y),
                      pack2(wc.z,wc.z), pack2(wc.w,wc.w) };
        #pragma unroll
        for (int o = 0; o < 8; o++) {
            acc[o][0] = fma2(wd[o], xp[0], acc[o][0]);
            acc[o][1] = fma2(wd[o], xp[1], acc[o][1]);
            acc[o][2] = fma2(wd[o], xp[2], acc[o][2]);
            acc[o][3] = fma2(wd[o], xp[3], acc[o][3]);
        }
    }

    const int ptq = lane >> 2;

    #pragma unroll
    for (int o = 0; o < 8; o++) {
        int og = o0 + o;
        float bv = bias[og];
        if (MODE == 2) {
            #pragma unroll
            for (int g = 0; g < 2; g++) {
                float h0, h1, h2, h3;
                unpack2(acc[o][2*g],   h0, h1);
                unpack2(acc[o][2*g+1], h2, h3);
                float pa = fmaxf(h0 + bv, 0.f) + fmaxf(h1 + bv, 0.f)
                         + fmaxf(h2 + bv, 0.f) + fmaxf(h3 + bv, 0.f);
                pa += __shfl_xor_sync(0xffffffffu, pa, 1);
                pa += __shfl_xor_sync(0xffffffffu, pa, 2);
                if ((lane & 3) == 0)
                    dst[og * TP + g * 8 + ptq] = pa;
            }
        } else {
            #pragma unroll
            for (int g = 0; g < 2; g++) {
                float h0, h1, h2, h3;
                unpack2(acc[o][2*g],   h0, h1);
                unpack2(acc[o][2*g+1], h2, h3);
                h0 = fmaxf(h0 + bv, 0.f);
                h1 = fmaxf(h1 + bv, 0.f);
                h2 = fmaxf(h2 + bv, 0.f);
                h3 = fmaxf(h3 + bv, 0.f);
                *(float4*)(dst + og * RR + g * 128 + lane * 4)
                    = make_float4(h0, h1, h2, h3);
            }
        }
    }
}

// ---------------------------------------------------------------------------
// Main kernel, 128 threads, TP=16 points (256 rows), 3 CTAs/SM.
// Smem (float offsets), 17504 floats = 68.4 KB:
//   0 sb1[32]  32 sb2[64]  96 red[64][16]  1120 XA[32][256]  9312 XB[32][256]
// ---------------------------------------------------------------------------
#define SMEM_FLOATS 17504

__global__ void __launch_bounds__(128, 3) main_kernel(
    const float* __restrict__ bb1, const float* __restrict__ bb2,
    float* __restrict__ out)
{
    extern __shared__ float sm[];
    float* sb1 = sm;
    float* sb2 = sm + 32;
    float* red = sm + 96;
    float* XA  = sm + 1120;
    float* XB  = sm + 9312;

    const int tid  = threadIdx.x;
    const int base = blockIdx.x * TP;
    const int b    = base >> 12;
    const int p0   = base & (NP - 1);

    if (tid < 32)      sb1[tid] = bb1[tid];
    else if (tid < 96) { int o = tid - 32; sb2[o] = bb2[o] * (1.0f / 16.0f); }

    // ---- staging: h0 = relu(Y0s[q] + A[p]) directly into XB [o][r] ----
    {
        int r0s = tid * 2;
        int pt  = r0s >> 4;
        int k0  = r0s & 15;
        size_t rowp = (size_t)b * NP + (p0 + pt);
        int2 qq = *(const int2*)(g_idx + (rowp << 4) + k0);
        const ulonglong2* Ap  = (const ulonglong2*)(gA  + rowp * 32);
        const ulonglong2* Yq0 = (const ulonglong2*)(gY0 + ((size_t)b * NP + qq.x) * 32);
        const ulonglong2* Yq1 = (const ulonglong2*)(gY0 + ((size_t)b * NP + qq.y) * 32);
        #pragma unroll
        for (int jj = 0; jj < 8; jj++) {
            ulonglong2 av = Ap[jj];
            ulonglong2 y0 = Yq0[jj];
            ulonglong2 y1 = Yq1[jj];
            int o = jj * 4;
            {
                u64 c0 = add2(y0.x, av.x), c1 = add2(y1.x, av.x);
                float a0, b0_, a1, b1_;
                unpack2(c0, a0, b0_); unpack2(c1, a1, b1_);
                *(u64*)(XB + (o+0) * RR + r0s) = pack2(fmaxf(a0, 0.f), fmaxf(a1, 0.f));
                *(u64*)(XB + (o+1) * RR + r0s) = pack2(fmaxf(b0_, 0.f), fmaxf(b1_, 0.f));
            }
            {
                u64 c0 = add2(y0.y, av.y), c1 = add2(y1.y, av.y);
                float a0, b0_, a1, b1_;
                unpack2(c0, a0, b0_); unpack2(c1, a1, b1_);
                *(u64*)(XB + (o+2) * RR + r0s) = pack2(fmaxf(a0, 0.f), fmaxf(a1, 0.f));
                *(u64*)(XB + (o+3) * RR + r0s) = pack2(fmaxf(b0_, 0.f), fmaxf(b1_, 0.f));
            }
        }
    }
    __syncthreads();

    const int w_   = tid >> 5;
    const int lane = tid & 31;

    gemm_stage<1>(XB, XA, g_w1T, 32, w_ * 8, sb1, lane);
    __syncthreads();
    gemm_stage<2>(XA, red, g_w2T, 64, w_ * 8,      sb2, lane);
    gemm_stage<2>(XA, red, g_w2T, 64, 32 + w_ * 8, sb2, lane);
    __syncthreads();

    // ---- epilogue: out = relu(SC[p] + red) ----
    {
        int pt  = tid & 15;
        int o0s = (tid >> 4) * 8;
        const float4* scp = (const float4*)(gSC + ((size_t)b * NP + p0 + pt) * 64 + o0s);
        float4 s0 = scp[0], s1 = scp[1];
        float scv[8] = { s0.x, s0.y, s0.z, s0.w, s1.x, s1.y, s1.z, s1.w };
        #pragma unroll
        for (int j = 0; j < 8; j++) {
            int o = o0s + j;
            float v = scv[j] + red[o * TP + pt];
            out[((size_t)b * 64 + o) * NP + p0 + pt] = fmaxf(v, 0.f);
        }
    }
}

// ---------------------------------------------------------------------------
extern "C" void kernel_launch(void* const* d_in, const int* in_sizes, int n_in,
                              void* d_out, int out_size)
{
    (void)in_sizes; (void)n_in; (void)out_size;
    const float* features = (const float*)d_in[1];
    const int*   ef       = (const int*)d_in[2];

    static bool attr_set = false;
    if (!attr_set) {
        cudaFuncSetAttribute(main_kernel,
                             cudaFuncAttributeMaxDynamicSharedMemorySize,
                             SMEM_FLOATS * (int)sizeof(float));
        attr_set = true;
    }

    wprep_kernel<<<28, 256>>>((const float*)d_in[3], (const float*)d_in[6],
                              (const float*)d_in[9], (const float*)d_in[12],
                              (const float*)d_in[4], (const float*)d_in[13],
                              (const float*)d_in[7], (const float*)d_in[10]);
    prep_kernel<<<BATCH * 256, 256>>>(ef);
    {
        dim3 tg(EDG / 256, BATCH);
        scatter_kernel<<<tg, 256>>>(ef);
    }
    {
        dim3 tb(32, 8), tg(NP / 32, BATCH);
        transpre_kernel<<<tg, tb>>>(features, (const float*)d_in[5],
                                    (const float*)d_in[14]);
    }
    main_kernel<<<(BATCH * NP) / TP, 128, SMEM_FLOATS * sizeof(float)>>>(
        (const float*)d_in[8], (const float*)d_in[11],
        (float*)d_out);
}